// round 9
// baseline (speedup 1.0000x reference)
#include <cuda_runtime.h>

#define N0_ 262144
#define N1_ 32768
#define N2_ 4096
#define EPS_ 1e-5f
typedef unsigned long long ull;

__device__ float4 g_data4[N0_];
__device__ float g_y0[N0_ * 24];
__device__ float g_y1[N1_ * 48];
__device__ float g_yc[3][N1_ * 48];
__device__ float g_y2[N1_ * 48];
__device__ float g_y3[N2_ * 96];
__device__ float g_y4[N2_ * 96];
__device__ float g_ye[3][N2_ * 96];
__device__ float g_psum[1024 * 96];
__device__ float g_psq [1024 * 96];
__device__ float g_scale[5 * 96];
__device__ float g_shift[5 * 96];
__device__ int   g_ctrs[8];

__device__ __forceinline__ ull fmaf2(ull a, ull b, ull c) {
    ull d;
    asm("fma.rn.f32x2 %0, %1, %2, %3;" : "=l"(d) : "l"(a), "l"(b), "l"(c));
    return d;
}
__device__ __forceinline__ ull dup2(float x) {
    ull d;
    asm("mov.b64 %0, {%1, %1};" : "=l"(d) : "f"(x));
    return d;
}
__device__ __forceinline__ float2 unp2(ull v) {
    float2 r;
    asm("mov.b64 {%0, %1}, %2;" : "=f"(r.x), "=f"(r.y) : "l"(v));
    return r;
}
__device__ __forceinline__ void cpa16(void* dst_smem, const void* src) {
    unsigned d = (unsigned)__cvta_generic_to_shared(dst_smem);
    asm volatile("cp.async.cg.shared.global [%0], [%1], 16;\n"
                 :: "r"(d), "l"(src));
}
__device__ __forceinline__ void cpa_commit() {
    asm volatile("cp.async.commit_group;\n");
}
template<int N> __device__ __forceinline__ void cpa_waitN() {
    asm volatile("cp.async.wait_group %0;\n" :: "n"(N));
}

// ---------------------------------------------------------------------------
// cp.async multi-stage pipelined gather-GEMM. Input must be PRE-NORMALIZED.
// Neighbor indices prefetched to SMEM (no dependent LDG on the issue path).
// sX row-major [MTILE][CCH]; sW [CCH][NTILE]; f32x2 pairs OUTPUT channels.
// ---------------------------------------------------------------------------
template<int K, int KSTR, int CIN, int CCH, int COUT, int NTILE, int MTILE,
         int MR, int NTH, int STAGES, bool STATS>
__global__ void __launch_bounds__(NTH)
conv_async(const float* __restrict__ xin, const int* __restrict__ neigh,
           const float* __restrict__ W,
           float* __restrict__ yout, float* __restrict__ psum,
           float* __restrict__ psq,
           const float* __restrict__ gamma, const float* __restrict__ beta,
           float* __restrict__ oscale, float* __restrict__ oshift,
           float invM, int* __restrict__ ctr)
{
    constexpr int NR = 4, NCG = NTILE / 4, NRG = MTILE / MR;
    static_assert(NTH == NCG * NRG, "layout");
    constexpr int NCHC  = CIN / CCH;
    constexpr int ITERS = K * NCHC;
    constexpr int CQ    = CCH / 4;
    constexpr int XCH   = MTILE * CQ;
    constexpr int XIT   = (XCH + NTH - 1) / NTH;
    constexpr bool XEX  = (XIT * NTH == XCH);
    constexpr int WCH   = CCH * (NTILE / 4);
    constexpr int WIT   = (WCH + NTH - 1) / NTH;
    constexpr bool WEX  = (WIT * NTH == WCH);
    constexpr int XB    = MTILE * CCH;
    constexpr int WB    = CCH * NTILE;
    constexpr int STG   = XB + WB;
    constexpr int NW    = NTH / 32;

    extern __shared__ float dsm[];           // STAGES * STG floats
    __shared__ int sIdx[MTILE * K];
    __shared__ int sLast;

    const int tid = threadIdx.x;
    const int cg  = tid % NCG, rg = tid / NCG;
    const int c0  = cg * NR, r0 = rg * MR;
    const int rowbase = blockIdx.x * MTILE;
    const int kofs = blockIdx.z * K;
    float* __restrict__ youtz =
        yout + (long)blockIdx.z * ((long)gridDim.x * MTILE) * COUT;

    // Prefetch all neighbor indices (coalesced-ish, one time)
    for (int i = tid; i < MTILE * K; i += NTH) {
        const int r = i / K, k = i % K;
        sIdx[i] = neigh[(long)(rowbase + r) * KSTR + kofs + k];
    }
    __syncthreads();

    auto issue = [&](int it, int stage) {
        const int k = it / NCHC, h = it % NCHC;
        float* sx = dsm + stage * STG;
        float* sw = sx + XB;
#pragma unroll
        for (int i = 0; i < XIT; i++) {
            const int o = tid + NTH * i;
            if (XEX || o < XCH) {
                const int r = o / CQ, q = o % CQ;
                const int idx = sIdx[r * K + k];
                cpa16(sx + r * CCH + q * 4,
                      xin + (long)idx * CIN + h * CCH + q * 4);
            }
        }
#pragma unroll
        for (int i = 0; i < WIT; i++) {
            const int o = tid + NTH * i;
            if (WEX || o < WCH) {
                const int c = o / (NTILE / 4), j4 = o % (NTILE / 4);
                cpa16(sw + c * NTILE + j4 * 4,
                      &W[((long)(kofs + k) * CIN + h * CCH + c) * COUT + j4 * 4]);
            }
        }
    };

    ull acc[MR][2];
#pragma unroll
    for (int m = 0; m < MR; m++) { acc[m][0] = 0ull; acc[m][1] = 0ull; }

#pragma unroll
    for (int s = 0; s < STAGES - 1; s++) {
        if (s < ITERS) issue(s, s);
        cpa_commit();
    }

    for (int it = 0; it < ITERS; it++) {
        cpa_waitN<STAGES - 2>();
        __syncthreads();
        const int nx = it + STAGES - 1;
        if (nx < ITERS) issue(nx, nx % STAGES);
        cpa_commit();

        const float* sx = dsm + (it % STAGES) * STG;
        const float* sw = sx + XB;
#pragma unroll 4
        for (int c4 = 0; c4 < CQ; c4++) {
            float4 xv[MR];
#pragma unroll
            for (int m = 0; m < MR; m++)
                xv[m] = *reinterpret_cast<const float4*>(
                    sx + (r0 + m) * CCH + c4 * 4);
#pragma unroll
            for (int cc = 0; cc < 4; cc++) {
                ulonglong2 w2 = *reinterpret_cast<const ulonglong2*>(
                    sw + (c4 * 4 + cc) * NTILE + c0);
#pragma unroll
                for (int m = 0; m < MR; m++) {
                    const ull xd = dup2((&xv[m].x)[cc]);
                    acc[m][0] = fmaf2(xd, w2.x, acc[m][0]);
                    acc[m][1] = fmaf2(xd, w2.y, acc[m][1]);
                }
            }
        }
    }

    float av[MR][NR];
#pragma unroll
    for (int m = 0; m < MR; m++) {
        float2 u0 = unp2(acc[m][0]), u1 = unp2(acc[m][1]);
        av[m][0] = u0.x; av[m][1] = u0.y; av[m][2] = u1.x; av[m][3] = u1.y;
        const long row = rowbase + r0 + m;
        *reinterpret_cast<float4*>(&youtz[row * COUT + c0]) =
            make_float4(av[m][0], av[m][1], av[m][2], av[m][3]);
    }

    if constexpr (STATS) {
        float (*sRed)[NTILE][2] = reinterpret_cast<float(*)[NTILE][2]>(dsm);
        __syncthreads();
#pragma unroll
        for (int j = 0; j < NR; j++) {
            float s = 0.f, q = 0.f;
#pragma unroll
            for (int m = 0; m < MR; m++) { s += av[m][j]; q += av[m][j]*av[m][j]; }
            sRed[rg][c0 + j][0] = s;
            sRed[rg][c0 + j][1] = q;
        }
        __syncthreads();
        if (tid < NTILE) {
            float s = 0.f, q = 0.f;
#pragma unroll
            for (int g = 0; g < NRG; g++) { s += sRed[g][tid][0]; q += sRed[g][tid][1]; }
            psum[(long)blockIdx.x * COUT + tid] = s;
            psq [(long)blockIdx.x * COUT + tid] = q;
        }
        __threadfence();
        __syncthreads();
        if (tid == 0) {
            int old = atomicAdd(ctr, 1);
            sLast = (old == (int)gridDim.x - 1);
        }
        __syncthreads();
        if (sLast) {
            __threadfence();
            const int lane = tid & 31, warp = tid >> 5;
            for (int d = warp; d < COUT; d += NW) {
                float s = 0.f, q = 0.f;
                for (int b = lane; b < (int)gridDim.x; b += 32) {
                    s += psum[(long)b * COUT + d];
                    q += psq [(long)b * COUT + d];
                }
#pragma unroll
                for (int off = 16; off > 0; off >>= 1) {
                    s += __shfl_down_sync(0xFFFFFFFFu, s, off);
                    q += __shfl_down_sync(0xFFFFFFFFu, q, off);
                }
                if (lane == 0) {
                    const float mean = s * invM;
                    const float var  = q * invM - mean * mean;
                    const float sc   = gamma[d] * rsqrtf(var + EPS_);
                    oscale[d] = sc;
                    oshift[d] = beta[d] - mean * sc;
                }
            }
            __syncthreads();
            if (tid == 0) *ctr = 0;
        }
    }
}

// BN+ReLU in place (vectorized).
template<int COUT>
__global__ void __launch_bounds__(256)
norm_relu(float4* __restrict__ y, const float* __restrict__ scale,
          const float* __restrict__ shift, int n4)
{
    const int i = blockIdx.x * 256 + threadIdx.x;
    if (i < n4) {
        const int c = (i % (COUT / 4)) * 4;
        float4 v = y[i];
        v.x = fmaxf(fmaf(v.x, __ldg(scale+c+0), __ldg(shift+c+0)), 0.f);
        v.y = fmaxf(fmaf(v.y, __ldg(scale+c+1), __ldg(shift+c+1)), 0.f);
        v.z = fmaxf(fmaf(v.z, __ldg(scale+c+2), __ldg(shift+c+2)), 0.f);
        v.w = fmaxf(fmaf(v.w, __ldg(scale+c+3), __ldg(shift+c+3)), 0.f);
        y[i] = v;
    }
}

// Combine P k-split partials -> y + BN finalize. NTH = COUT, R rows/block.
template<int COUT, int P, int R>
__global__ void __launch_bounds__(COUT)
combine_bn(const float* __restrict__ parts, long pstride, float* __restrict__ y,
           float* __restrict__ psum, float* __restrict__ psq,
           const float* __restrict__ gamma, const float* __restrict__ beta,
           float* __restrict__ oscale, float* __restrict__ oshift,
           float invM, int* __restrict__ ctr)
{
    __shared__ int sLast;
    const int c = threadIdx.x;
    const int rbase = blockIdx.x * R;
    float s = 0.f, q = 0.f;
    for (int r = rbase; r < rbase + R; r++) {
        const long i = (long)r * COUT + c;
        float v = 0.f;
#pragma unroll
        for (int p = 0; p < P; p++) v += parts[p * pstride + i];
        y[i] = v;
        s += v; q += v * v;
    }
    psum[(long)blockIdx.x * COUT + c] = s;
    psq [(long)blockIdx.x * COUT + c] = q;
    __threadfence();
    __syncthreads();
    if (c == 0) {
        int old = atomicAdd(ctr, 1);
        sLast = (old == (int)gridDim.x - 1);
    }
    __syncthreads();
    if (sLast) {
        __threadfence();
        float ss = 0.f, qq = 0.f;
        for (int b = 0; b < (int)gridDim.x; b++) {
            ss += psum[(long)b * COUT + c];
            qq += psq [(long)b * COUT + c];
        }
        const float mean = ss * invM;
        const float var  = qq * invM - mean * mean;
        const float sc   = gamma[c] * rsqrtf(var + EPS_);
        oscale[c] = sc;
        oshift[c] = beta[c] - mean * sc;
        __syncthreads();
        if (c == 0) *ctr = 0;
    }
}

// Stage A: padded float4 rows, one thread per row, f32x2 channel pairs.
__global__ void __launch_bounds__(256)
conv_stageA(const float4* __restrict__ x4, const int* __restrict__ neigh,
            const float* __restrict__ W, float* __restrict__ yout,
            float* __restrict__ psum, float* __restrict__ psq,
            const float* __restrict__ gamma, const float* __restrict__ beta,
            float* __restrict__ oscale, float* __restrict__ oshift,
            float invM, int* __restrict__ ctr)
{
    __shared__ float sW[27 * 3 * 24];
    __shared__ int   sIdx[256 * 27];
    __shared__ float sRed[8][24][2];
    __shared__ int   sLast;

    const int tid = threadIdx.x;
    const int row = blockIdx.x * 256 + tid;

    for (int i = tid; i < 27 * 3 * 24; i += 256) sW[i] = W[i];
    const long nbase = (long)blockIdx.x * 256 * 27;
    for (int i = tid; i < 256 * 27; i += 256) sIdx[i] = neigh[nbase + i];
    __syncthreads();

    ull a2[12];
#pragma unroll
    for (int j = 0; j < 12; j++) a2[j] = 0ull;

#pragma unroll 3
    for (int k = 0; k < 27; k++) {
        float4 xv = x4[sIdx[tid * 27 + k]];
        const float v[3] = {xv.x, xv.y, xv.z};
#pragma unroll
        for (int c = 0; c < 3; c++) {
            const ull xd = dup2(v[c]);
            const ulonglong2* wr =
                reinterpret_cast<const ulonglong2*>(&sW[(k * 3 + c) * 24]);
#pragma unroll
            for (int t = 0; t < 6; t++) {
                ulonglong2 wp = wr[t];
                a2[2*t+0] = fmaf2(xd, wp.x, a2[2*t+0]);
                a2[2*t+1] = fmaf2(xd, wp.y, a2[2*t+1]);
            }
        }
    }

    float acc[24];
#pragma unroll
    for (int j = 0; j < 12; j++) {
        float2 u = unp2(a2[j]);
        acc[2*j] = u.x; acc[2*j+1] = u.y;
    }
#pragma unroll
    for (int j = 0; j < 24; j += 4)
        *reinterpret_cast<float4*>(&yout[(long)row * 24 + j]) =
            make_float4(acc[j], acc[j+1], acc[j+2], acc[j+3]);

    const int lane = tid & 31, warp = tid >> 5;
#pragma unroll
    for (int j = 0; j < 24; j++) {
        float s = acc[j], q = acc[j] * acc[j];
#pragma unroll
        for (int off = 16; off > 0; off >>= 1) {
            s += __shfl_down_sync(0xFFFFFFFFu, s, off);
            q += __shfl_down_sync(0xFFFFFFFFu, q, off);
        }
        if (lane == 0) { sRed[warp][j][0] = s; sRed[warp][j][1] = q; }
    }
    __syncthreads();
    if (tid < 24) {
        float s = 0.f, q = 0.f;
#pragma unroll
        for (int w = 0; w < 8; w++) { s += sRed[w][tid][0]; q += sRed[w][tid][1]; }
        psum[(long)blockIdx.x * 24 + tid] = s;
        psq [(long)blockIdx.x * 24 + tid] = q;
    }
    __threadfence();
    __syncthreads();
    if (tid == 0) {
        int old = atomicAdd(ctr, 1);
        sLast = (old == (int)gridDim.x - 1);
    }
    __syncthreads();
    if (sLast) {
        __threadfence();
        for (int d = warp; d < 24; d += 8) {
            float s = 0.f, q = 0.f;
            for (int b = lane; b < (int)gridDim.x; b += 32) {
                s += psum[(long)b * 24 + d];
                q += psq [(long)b * 24 + d];
            }
#pragma unroll
            for (int off = 16; off > 0; off >>= 1) {
                s += __shfl_down_sync(0xFFFFFFFFu, s, off);
                q += __shfl_down_sync(0xFFFFFFFFu, q, off);
            }
            if (lane == 0) {
                const float mean = s * invM;
                const float var  = q * invM - mean * mean;
                const float sc   = gamma[d] * rsqrtf(var + EPS_);
                oscale[d] = sc;
                oshift[d] = beta[d] - mean * sc;
            }
        }
        __syncthreads();
        if (tid == 0) *ctr = 0;
    }
}

__global__ void pad4_kernel(const float* __restrict__ d, float4* __restrict__ o)
{
    const int i = blockIdx.x * 256 + threadIdx.x;
    if (i < N0_)
        o[i] = make_float4(d[3*i], d[3*i+1], d[3*i+2], 0.f);
}

__global__ void final_norm(const float* __restrict__ y,
                           const float* __restrict__ scale,
                           const float* __restrict__ shift,
                           float* __restrict__ out, int total, int cout)
{
    const int i = blockIdx.x * 256 + threadIdx.x;
    if (i < total) {
        const int d = i % cout;
        out[i] = fmaxf(fmaf(y[i], scale[d], shift[d]), 0.f);
    }
}

extern "C" void kernel_launch(void* const* d_in, const int* in_sizes, int n_in,
                              void* d_out, int out_size)
{
    const float* data   = (const float*)d_in[0];
    const int*   neigh0 = (const int*)  d_in[1];
    const int*   child0 = (const int*)  d_in[2];
    const int*   neigh1 = (const int*)  d_in[3];
    const int*   child1 = (const int*)  d_in[4];
    const int*   neigh2 = (const int*)  d_in[5];
    const float* w0  = (const float*)d_in[6];
    const float* g0  = (const float*)d_in[7];
    const float* b0  = (const float*)d_in[8];
    const float* wd0 = (const float*)d_in[9];
    const float* gd0 = (const float*)d_in[10];
    const float* bd0 = (const float*)d_in[11];
    const float* w1  = (const float*)d_in[12];
    const float* g1  = (const float*)d_in[13];
    const float* b1  = (const float*)d_in[14];
    const float* wd1 = (const float*)d_in[15];
    const float* gd1 = (const float*)d_in[16];
    const float* bd1 = (const float*)d_in[17];
    const float* wp  = (const float*)d_in[18];
    const float* gp  = (const float*)d_in[19];
    const float* bp  = (const float*)d_in[20];

    float4 *x4;
    float *y0,*y1,*yc,*y2,*y3,*y4,*ye,*psum,*psq,*scl,*shf; int *ctrs;
    cudaGetSymbolAddress((void**)&x4,   g_data4);
    cudaGetSymbolAddress((void**)&y0,   g_y0);
    cudaGetSymbolAddress((void**)&y1,   g_y1);
    cudaGetSymbolAddress((void**)&yc,   g_yc);
    cudaGetSymbolAddress((void**)&y2,   g_y2);
    cudaGetSymbolAddress((void**)&y3,   g_y3);
    cudaGetSymbolAddress((void**)&y4,   g_y4);
    cudaGetSymbolAddress((void**)&ye,   g_ye);
    cudaGetSymbolAddress((void**)&psum, g_psum);
    cudaGetSymbolAddress((void**)&psq,  g_psq);
    cudaGetSymbolAddress((void**)&scl,  g_scale);
    cudaGetSymbolAddress((void**)&shf,  g_shift);
    cudaGetSymbolAddress((void**)&ctrs, g_ctrs);

    auto kB = conv_async<8, 8, 24, 24, 48, 48, 64, 4, 192, 4, true>;
    auto kC = conv_async<9, 27, 48, 48, 48, 48, 128, 4, 384, 3, false>;
    auto kD = conv_async<8, 8, 48, 48, 96, 96, 32, 4, 192, 4, true>;
    auto kE = conv_async<9, 27, 96, 48, 96, 96, 32, 4, 192, 3, false>;
    const int smB = 4 * (64*24 + 24*48) * 4;
    const int smC = 3 * (128*48 + 48*48) * 4;
    const int smD = 4 * (32*48 + 48*96) * 4;
    const int smE = 3 * (32*48 + 48*96) * 4;
    cudaFuncSetAttribute(kB, cudaFuncAttributeMaxDynamicSharedMemorySize, smB);
    cudaFuncSetAttribute(kC, cudaFuncAttributeMaxDynamicSharedMemorySize, smC);
    cudaFuncSetAttribute(kD, cudaFuncAttributeMaxDynamicSharedMemorySize, smD);
    cudaFuncSetAttribute(kE, cudaFuncAttributeMaxDynamicSharedMemorySize, smE);

    // 0: pad input rows to float4
    pad4_kernel<<<(N0_ + 255) / 256, 256>>>(data, x4);

    // 1: Stage A -> y0 raw + BN0
    conv_stageA<<<N0_/256, 256>>>(x4, neigh0, w0, y0, psum, psq,
                                  g0, b0, scl, shf, 1.f / N0_, ctrs + 0);
    // 2: normalize y0
    norm_relu<24><<<(N0_*24/4 + 255)/256, 256>>>(
        (float4*)y0, scl, shf, N0_*24/4);

    // 3: Stage B -> y1 raw + BN1
    kB<<<dim3(N1_/64, 1, 1), 192, smB>>>(
        y0, child0, wd0, y1, psum, psq,
        gd0, bd0, scl + 96, shf + 96, 1.f / N1_, ctrs + 1);
    // 4: normalize y1
    norm_relu<48><<<(N1_*48/4 + 255)/256, 256>>>(
        (float4*)y1, scl + 96, shf + 96, N1_*48/4);

    // 5: Stage C conv, k-split x3 -> yc partials   (ncu target)
    kC<<<dim3(N1_/128, 1, 3), 384, smC>>>(
        y1, neigh1, w1, yc, nullptr, nullptr,
        nullptr, nullptr, nullptr, nullptr, 0.f, nullptr);
    // 6: combine -> y2 raw + BN2
    combine_bn<48, 3, 64><<<N1_/64, 48>>>(
        yc, (long)N1_ * 48, y2, psum, psq,
        g1, b1, scl + 192, shf + 192, 1.f / N1_, ctrs + 2);
    // 7: normalize y2
    norm_relu<48><<<(N1_*48/4 + 255)/256, 256>>>(
        (float4*)y2, scl + 192, shf + 192, N1_*48/4);

    // 8: Stage D -> y3 raw + BN3
    kD<<<dim3(N2_/32, 1, 1), 192, smD>>>(
        y2, child1, wd1, y3, psum, psq,
        gd1, bd1, scl + 288, shf + 288, 1.f / N2_, ctrs + 3);
    // 9: normalize y3
    norm_relu<96><<<(N2_*96/4 + 255)/256, 256>>>(
        (float4*)y3, scl + 288, shf + 288, N2_*96/4);

    // 10: Stage E conv, k-split x3 -> ye partials
    kE<<<dim3(N2_/32, 1, 3), 192, smE>>>(
        y3, neigh2, wp, ye, nullptr, nullptr,
        nullptr, nullptr, nullptr, nullptr, 0.f, nullptr);

    // 11: combine -> y4 raw + BN4
    combine_bn<96, 3, 64><<<N2_/64, 96>>>(
        ye, (long)N2_ * 96, y4, psum, psq,
        gp, bp, scl + 384, shf + 384, 1.f / N2_, ctrs + 5);

    // 12: final BN + ReLU -> d_out
    final_norm<<<(N2_ * 96 + 255) / 256, 256>>>(
        y4, scl + 384, shf + 384, (float*)d_out, N2_ * 96, 96);
}

// round 10
// speedup vs baseline: 1.0989x; 1.0989x over previous
#include <cuda_runtime.h>

#define N0_ 262144
#define N1_ 32768
#define N2_ 4096
#define EPS_ 1e-5f
typedef unsigned long long ull;

__device__ float4 g_data4[N0_];
__device__ float g_y0[N0_ * 24];
__device__ float g_y1[N1_ * 48];
__device__ float g_yc[3][N1_ * 48];
__device__ float g_y2[N1_ * 48];
__device__ float g_y3[N2_ * 96];
__device__ float g_y4[N2_ * 96];
__device__ float g_ye[3][N2_ * 96];
__device__ float g_psum[1024 * 96];
__device__ float g_psq [1024 * 96];
__device__ float g_scale[5 * 96];
__device__ float g_shift[5 * 96];
__device__ int   g_ctrs[8];

__device__ __forceinline__ ull fmaf2(ull a, ull b, ull c) {
    ull d;
    asm("fma.rn.f32x2 %0, %1, %2, %3;" : "=l"(d) : "l"(a), "l"(b), "l"(c));
    return d;
}
__device__ __forceinline__ ull dup2(float x) {
    ull d;
    asm("mov.b64 %0, {%1, %1};" : "=l"(d) : "f"(x));
    return d;
}
__device__ __forceinline__ float2 unp2(ull v) {
    float2 r;
    asm("mov.b64 {%0, %1}, %2;" : "=f"(r.x), "=f"(r.y) : "l"(v));
    return r;
}
__device__ __forceinline__ void cpa16(void* dst_smem, const void* src) {
    unsigned d = (unsigned)__cvta_generic_to_shared(dst_smem);
    asm volatile("cp.async.cg.shared.global [%0], [%1], 16;\n"
                 :: "r"(d), "l"(src));
}
__device__ __forceinline__ void cpa_commit() {
    asm volatile("cp.async.commit_group;\n");
}
__device__ __forceinline__ void cpa_wait1() {
    asm volatile("cp.async.wait_group 1;\n");
}

// ---------------------------------------------------------------------------
// cp.async 3-stage pipelined gather-GEMM (R8-proven). Input PRE-NORMALIZED.
// sX row-major [MTILE][CCH]; sW [CCH][NTILE]. f32x2 pairs OUTPUT channels.
// ---------------------------------------------------------------------------
template<int K, int KSTR, int CIN, int CCH, int COUT, int NTILE, int MTILE,
         int MR, int NTH, bool STATS>
__global__ void __launch_bounds__(NTH)
conv_async(const float* __restrict__ xin, const int* __restrict__ neigh,
           const float* __restrict__ W,
           float* __restrict__ yout, float* __restrict__ psum,
           float* __restrict__ psq,
           const float* __restrict__ gamma, const float* __restrict__ beta,
           float* __restrict__ oscale, float* __restrict__ oshift,
           float invM, int* __restrict__ ctr)
{
    constexpr int NR = 4, NCG = NTILE / 4, NRG = MTILE / MR;
    static_assert(NTH == NCG * NRG, "layout");
    constexpr int NCHC  = CIN / CCH;
    constexpr int ITERS = K * NCHC;
    constexpr int CQ    = CCH / 4;
    constexpr int XCH   = MTILE * CQ;
    constexpr int XIT   = (XCH + NTH - 1) / NTH;
    constexpr bool XEX  = (XIT * NTH == XCH);
    constexpr int WCH   = CCH * (NTILE / 4);
    constexpr int WIT   = (WCH + NTH - 1) / NTH;
    constexpr bool WEX  = (WIT * NTH == WCH);
    constexpr int XB    = MTILE * CCH;
    constexpr int WB    = CCH * NTILE;
    constexpr int STG   = XB + WB;
    constexpr int NW    = NTH / 32;

    extern __shared__ float dsm[];           // 3 * STG floats
    __shared__ int sLast;

    const int tid = threadIdx.x;
    const int cg  = tid % NCG, rg = tid / NCG;
    const int c0  = cg * NR, r0 = rg * MR;
    const int rowbase = blockIdx.x * MTILE;
    const int kofs = blockIdx.z * K;
    float* __restrict__ youtz =
        yout + (long)blockIdx.z * ((long)gridDim.x * MTILE) * COUT;

    auto issue = [&](int it, int stage) {
        const int k = it / NCHC, h = it % NCHC;
        float* sx = dsm + stage * STG;
        float* sw = sx + XB;
#pragma unroll
        for (int i = 0; i < XIT; i++) {
            const int o = tid + NTH * i;
            if (XEX || o < XCH) {
                const int r = o / CQ, q = o % CQ;
                const int idx = __ldg(&neigh[(long)(rowbase + r) * KSTR + kofs + k]);
                cpa16(sx + r * CCH + q * 4,
                      xin + (long)idx * CIN + h * CCH + q * 4);
            }
        }
#pragma unroll
        for (int i = 0; i < WIT; i++) {
            const int o = tid + NTH * i;
            if (WEX || o < WCH) {
                const int c = o / (NTILE / 4), j4 = o % (NTILE / 4);
                cpa16(sw + c * NTILE + j4 * 4,
                      &W[((long)(kofs + k) * CIN + h * CCH + c) * COUT + j4 * 4]);
            }
        }
    };

    ull acc[MR][2];
#pragma unroll
    for (int m = 0; m < MR; m++) { acc[m][0] = 0ull; acc[m][1] = 0ull; }

    issue(0, 0); cpa_commit();
    if (ITERS > 1) issue(1, 1);
    cpa_commit();

    for (int it = 0; it < ITERS; it++) {
        cpa_wait1();
        __syncthreads();
        if (it + 2 < ITERS) issue(it + 2, (it + 2) % 3);
        cpa_commit();

        const float* sx = dsm + (it % 3) * STG;
        const float* sw = sx + XB;
#pragma unroll 4
        for (int c4 = 0; c4 < CQ; c4++) {
            float4 xv[MR];
#pragma unroll
            for (int m = 0; m < MR; m++)
                xv[m] = *reinterpret_cast<const float4*>(
                    sx + (r0 + m) * CCH + c4 * 4);
#pragma unroll
            for (int cc = 0; cc < 4; cc++) {
                ulonglong2 w2 = *reinterpret_cast<const ulonglong2*>(
                    sw + (c4 * 4 + cc) * NTILE + c0);
#pragma unroll
                for (int m = 0; m < MR; m++) {
                    const ull xd = dup2((&xv[m].x)[cc]);
                    acc[m][0] = fmaf2(xd, w2.x, acc[m][0]);
                    acc[m][1] = fmaf2(xd, w2.y, acc[m][1]);
                }
            }
        }
    }

    float av[MR][NR];
#pragma unroll
    for (int m = 0; m < MR; m++) {
        float2 u0 = unp2(acc[m][0]), u1 = unp2(acc[m][1]);
        av[m][0] = u0.x; av[m][1] = u0.y; av[m][2] = u1.x; av[m][3] = u1.y;
        const long row = rowbase + r0 + m;
        *reinterpret_cast<float4*>(&youtz[row * COUT + c0]) =
            make_float4(av[m][0], av[m][1], av[m][2], av[m][3]);
    }

    if constexpr (STATS) {
        float (*sRed)[NTILE][2] = reinterpret_cast<float(*)[NTILE][2]>(dsm);
        __syncthreads();
#pragma unroll
        for (int j = 0; j < NR; j++) {
            float s = 0.f, q = 0.f;
#pragma unroll
            for (int m = 0; m < MR; m++) { s += av[m][j]; q += av[m][j]*av[m][j]; }
            sRed[rg][c0 + j][0] = s;
            sRed[rg][c0 + j][1] = q;
        }
        __syncthreads();
        if (tid < NTILE) {
            float s = 0.f, q = 0.f;
#pragma unroll
            for (int g = 0; g < NRG; g++) { s += sRed[g][tid][0]; q += sRed[g][tid][1]; }
            psum[(long)blockIdx.x * COUT + tid] = s;
            psq [(long)blockIdx.x * COUT + tid] = q;
        }
        __threadfence();
        __syncthreads();
        if (tid == 0) {
            int old = atomicAdd(ctr, 1);
            sLast = (old == (int)gridDim.x - 1);
        }
        __syncthreads();
        if (sLast) {
            __threadfence();
            const int lane = tid & 31, warp = tid >> 5;
            for (int d = warp; d < COUT; d += NW) {
                float s = 0.f, q = 0.f;
                for (int b = lane; b < (int)gridDim.x; b += 32) {
                    s += psum[(long)b * COUT + d];
                    q += psq [(long)b * COUT + d];
                }
#pragma unroll
                for (int off = 16; off > 0; off >>= 1) {
                    s += __shfl_down_sync(0xFFFFFFFFu, s, off);
                    q += __shfl_down_sync(0xFFFFFFFFu, q, off);
                }
                if (lane == 0) {
                    const float mean = s * invM;
                    const float var  = q * invM - mean * mean;
                    const float sc   = gamma[d] * rsqrtf(var + EPS_);
                    oscale[d] = sc;
                    oshift[d] = beta[d] - mean * sc;
                }
            }
            __syncthreads();
            if (tid == 0) *ctr = 0;
        }
    }
}

// BN+ReLU in place (vectorized).
template<int COUT>
__global__ void __launch_bounds__(256)
norm_relu(float4* __restrict__ y, const float* __restrict__ scale,
          const float* __restrict__ shift, int n4)
{
    const int i = blockIdx.x * 256 + threadIdx.x;
    if (i < n4) {
        const int c = (i % (COUT / 4)) * 4;
        float4 v = y[i];
        v.x = fmaxf(fmaf(v.x, __ldg(scale+c+0), __ldg(shift+c+0)), 0.f);
        v.y = fmaxf(fmaf(v.y, __ldg(scale+c+1), __ldg(shift+c+1)), 0.f);
        v.z = fmaxf(fmaf(v.z, __ldg(scale+c+2), __ldg(shift+c+2)), 0.f);
        v.w = fmaxf(fmaf(v.w, __ldg(scale+c+3), __ldg(shift+c+3)), 0.f);
        y[i] = v;
    }
}

// Combine P k-split partials -> y + BN finalize. NTH = COUT, R rows/block.
template<int COUT, int P, int R>
__global__ void __launch_bounds__(COUT)
combine_bn(const float* __restrict__ parts, long pstride, float* __restrict__ y,
           float* __restrict__ psum, float* __restrict__ psq,
           const float* __restrict__ gamma, const float* __restrict__ beta,
           float* __restrict__ oscale, float* __restrict__ oshift,
           float invM, int* __restrict__ ctr)
{
    __shared__ int sLast;
    const int c = threadIdx.x;
    const int rbase = blockIdx.x * R;
    float s = 0.f, q = 0.f;
    for (int r = rbase; r < rbase + R; r++) {
        const long i = (long)r * COUT + c;
        float v = 0.f;
#pragma unroll
        for (int p = 0; p < P; p++) v += parts[p * pstride + i];
        y[i] = v;
        s += v; q += v * v;
    }
    psum[(long)blockIdx.x * COUT + c] = s;
    psq [(long)blockIdx.x * COUT + c] = q;
    __threadfence();
    __syncthreads();
    if (c == 0) {
        int old = atomicAdd(ctr, 1);
        sLast = (old == (int)gridDim.x - 1);
    }
    __syncthreads();
    if (sLast) {
        __threadfence();
        float ss = 0.f, qq = 0.f;
        for (int b = 0; b < (int)gridDim.x; b++) {
            ss += psum[(long)b * COUT + c];
            qq += psq [(long)b * COUT + c];
        }
        const float mean = ss * invM;
        const float var  = qq * invM - mean * mean;
        const float sc   = gamma[c] * rsqrtf(var + EPS_);
        oscale[c] = sc;
        oshift[c] = beta[c] - mean * sc;
        __syncthreads();
        if (c == 0) *ctr = 0;
    }
}

// Stage A: padded float4 rows, one thread per row, f32x2 channel pairs.
__global__ void __launch_bounds__(256)
conv_stageA(const float4* __restrict__ x4, const int* __restrict__ neigh,
            const float* __restrict__ W, float* __restrict__ yout,
            float* __restrict__ psum, float* __restrict__ psq,
            const float* __restrict__ gamma, const float* __restrict__ beta,
            float* __restrict__ oscale, float* __restrict__ oshift,
            float invM, int* __restrict__ ctr)
{
    __shared__ float sW[27 * 3 * 24];
    __shared__ int   sIdx[256 * 27];
    __shared__ float sRed[8][24][2];
    __shared__ int   sLast;

    const int tid = threadIdx.x;
    const int row = blockIdx.x * 256 + tid;

    for (int i = tid; i < 27 * 3 * 24; i += 256) sW[i] = W[i];
    const long nbase = (long)blockIdx.x * 256 * 27;
    for (int i = tid; i < 256 * 27; i += 256) sIdx[i] = neigh[nbase + i];
    __syncthreads();

    ull a2[12];
#pragma unroll
    for (int j = 0; j < 12; j++) a2[j] = 0ull;

#pragma unroll 3
    for (int k = 0; k < 27; k++) {
        float4 xv = x4[sIdx[tid * 27 + k]];
        const float v[3] = {xv.x, xv.y, xv.z};
#pragma unroll
        for (int c = 0; c < 3; c++) {
            const ull xd = dup2(v[c]);
            const ulonglong2* wr =
                reinterpret_cast<const ulonglong2*>(&sW[(k * 3 + c) * 24]);
#pragma unroll
            for (int t = 0; t < 6; t++) {
                ulonglong2 wp = wr[t];
                a2[2*t+0] = fmaf2(xd, wp.x, a2[2*t+0]);
                a2[2*t+1] = fmaf2(xd, wp.y, a2[2*t+1]);
            }
        }
    }

    float acc[24];
#pragma unroll
    for (int j = 0; j < 12; j++) {
        float2 u = unp2(a2[j]);
        acc[2*j] = u.x; acc[2*j+1] = u.y;
    }
#pragma unroll
    for (int j = 0; j < 24; j += 4)
        *reinterpret_cast<float4*>(&yout[(long)row * 24 + j]) =
            make_float4(acc[j], acc[j+1], acc[j+2], acc[j+3]);

    const int lane = tid & 31, warp = tid >> 5;
#pragma unroll
    for (int j = 0; j < 24; j++) {
        float s = acc[j], q = acc[j] * acc[j];
#pragma unroll
        for (int off = 16; off > 0; off >>= 1) {
            s += __shfl_down_sync(0xFFFFFFFFu, s, off);
            q += __shfl_down_sync(0xFFFFFFFFu, q, off);
        }
        if (lane == 0) { sRed[warp][j][0] = s; sRed[warp][j][1] = q; }
    }
    __syncthreads();
    if (tid < 24) {
        float s = 0.f, q = 0.f;
#pragma unroll
        for (int w = 0; w < 8; w++) { s += sRed[w][tid][0]; q += sRed[w][tid][1]; }
        psum[(long)blockIdx.x * 24 + tid] = s;
        psq [(long)blockIdx.x * 24 + tid] = q;
    }
    __threadfence();
    __syncthreads();
    if (tid == 0) {
        int old = atomicAdd(ctr, 1);
        sLast = (old == (int)gridDim.x - 1);
    }
    __syncthreads();
    if (sLast) {
        __threadfence();
        for (int d = warp; d < 24; d += 8) {
            float s = 0.f, q = 0.f;
            for (int b = lane; b < (int)gridDim.x; b += 32) {
                s += psum[(long)b * 24 + d];
                q += psq [(long)b * 24 + d];
            }
#pragma unroll
            for (int off = 16; off > 0; off >>= 1) {
                s += __shfl_down_sync(0xFFFFFFFFu, s, off);
                q += __shfl_down_sync(0xFFFFFFFFu, q, off);
            }
            if (lane == 0) {
                const float mean = s * invM;
                const float var  = q * invM - mean * mean;
                const float sc   = gamma[d] * rsqrtf(var + EPS_);
                oscale[d] = sc;
                oshift[d] = beta[d] - mean * sc;
            }
        }
        __syncthreads();
        if (tid == 0) *ctr = 0;
    }
}

__global__ void pad4_kernel(const float* __restrict__ d, float4* __restrict__ o)
{
    const int i = blockIdx.x * 256 + threadIdx.x;
    if (i < N0_)
        o[i] = make_float4(d[3*i], d[3*i+1], d[3*i+2], 0.f);
}

__global__ void final_norm(const float* __restrict__ y,
                           const float* __restrict__ scale,
                           const float* __restrict__ shift,
                           float* __restrict__ out, int total, int cout)
{
    const int i = blockIdx.x * 256 + threadIdx.x;
    if (i < total) {
        const int d = i % cout;
        out[i] = fmaxf(fmaf(y[i], scale[d], shift[d]), 0.f);
    }
}

extern "C" void kernel_launch(void* const* d_in, const int* in_sizes, int n_in,
                              void* d_out, int out_size)
{
    const float* data   = (const float*)d_in[0];
    const int*   neigh0 = (const int*)  d_in[1];
    const int*   child0 = (const int*)  d_in[2];
    const int*   neigh1 = (const int*)  d_in[3];
    const int*   child1 = (const int*)  d_in[4];
    const int*   neigh2 = (const int*)  d_in[5];
    const float* w0  = (const float*)d_in[6];
    const float* g0  = (const float*)d_in[7];
    const float* b0  = (const float*)d_in[8];
    const float* wd0 = (const float*)d_in[9];
    const float* gd0 = (const float*)d_in[10];
    const float* bd0 = (const float*)d_in[11];
    const float* w1  = (const float*)d_in[12];
    const float* g1  = (const float*)d_in[13];
    const float* b1  = (const float*)d_in[14];
    const float* wd1 = (const float*)d_in[15];
    const float* gd1 = (const float*)d_in[16];
    const float* bd1 = (const float*)d_in[17];
    const float* wp  = (const float*)d_in[18];
    const float* gp  = (const float*)d_in[19];
    const float* bp  = (const float*)d_in[20];

    float4 *x4;
    float *y0,*y1,*yc,*y2,*y3,*y4,*ye,*psum,*psq,*scl,*shf; int *ctrs;
    cudaGetSymbolAddress((void**)&x4,   g_data4);
    cudaGetSymbolAddress((void**)&y0,   g_y0);
    cudaGetSymbolAddress((void**)&y1,   g_y1);
    cudaGetSymbolAddress((void**)&yc,   g_yc);
    cudaGetSymbolAddress((void**)&y2,   g_y2);
    cudaGetSymbolAddress((void**)&y3,   g_y3);
    cudaGetSymbolAddress((void**)&y4,   g_y4);
    cudaGetSymbolAddress((void**)&ye,   g_ye);
    cudaGetSymbolAddress((void**)&psum, g_psum);
    cudaGetSymbolAddress((void**)&psq,  g_psq);
    cudaGetSymbolAddress((void**)&scl,  g_scale);
    cudaGetSymbolAddress((void**)&shf,  g_shift);
    cudaGetSymbolAddress((void**)&ctrs, g_ctrs);

    auto kB = conv_async<8, 8, 24, 24, 48, 48, 64, 4, 192, true>;
    auto kC = conv_async<9, 27, 48, 24, 48, 48, 64, 4, 192, false>;
    auto kD = conv_async<8, 8, 48, 48, 96, 96, 32, 4, 192, true>;
    auto kE = conv_async<9, 27, 96, 48, 96, 96, 32, 4, 192, false>;
    const int smB = 3 * (64*24 + 24*48) * 4;
    const int smC = 3 * (64*24 + 24*48) * 4;
    const int smD = 3 * (32*48 + 48*96) * 4;
    const int smE = smD;
    cudaFuncSetAttribute(kB, cudaFuncAttributeMaxDynamicSharedMemorySize, smB);
    cudaFuncSetAttribute(kC, cudaFuncAttributeMaxDynamicSharedMemorySize, smC);
    cudaFuncSetAttribute(kD, cudaFuncAttributeMaxDynamicSharedMemorySize, smD);
    cudaFuncSetAttribute(kE, cudaFuncAttributeMaxDynamicSharedMemorySize, smE);

    // 0: pad input rows to float4
    pad4_kernel<<<(N0_ + 255) / 256, 256>>>(data, x4);

    // 1: Stage A -> y0 raw + BN0
    conv_stageA<<<N0_/256, 256>>>(x4, neigh0, w0, y0, psum, psq,
                                  g0, b0, scl, shf, 1.f / N0_, ctrs + 0);
    // 2: normalize y0
    norm_relu<24><<<(N0_*24/4 + 255)/256, 256>>>(
        (float4*)y0, scl, shf, N0_*24/4);

    // 3: Stage B -> y1 raw + BN1
    kB<<<dim3(N1_/64, 1, 1), 192, smB>>>(
        y0, child0, wd0, y1, psum, psq,
        gd0, bd0, scl + 96, shf + 96, 1.f / N1_, ctrs + 1);
    // 4: normalize y1
    norm_relu<48><<<(N1_*48/4 + 255)/256, 256>>>(
        (float4*)y1, scl + 96, shf + 96, N1_*48/4);

    // 5: Stage C conv, k-split x3 -> yc partials   (ncu target)
    kC<<<dim3(N1_/64, 1, 3), 192, smC>>>(
        y1, neigh1, w1, yc, nullptr, nullptr,
        nullptr, nullptr, nullptr, nullptr, 0.f, nullptr);
    // 6: combine -> y2 raw + BN2
    combine_bn<48, 3, 64><<<N1_/64, 48>>>(
        yc, (long)N1_ * 48, y2, psum, psq,
        g1, b1, scl + 192, shf + 192, 1.f / N1_, ctrs + 2);
    // 7: normalize y2
    norm_relu<48><<<(N1_*48/4 + 255)/256, 256>>>(
        (float4*)y2, scl + 192, shf + 192, N1_*48/4);

    // 8: Stage D -> y3 raw + BN3
    kD<<<dim3(N2_/32, 1, 1), 192, smD>>>(
        y2, child1, wd1, y3, psum, psq,
        gd1, bd1, scl + 288, shf + 288, 1.f / N2_, ctrs + 3);
    // 9: normalize y3
    norm_relu<96><<<(N2_*96/4 + 255)/256, 256>>>(
        (float4*)y3, scl + 288, shf + 288, N2_*96/4);

    // 10: Stage E conv, k-split x3 -> ye partials
    kE<<<dim3(N2_/32, 1, 3), 192, smE>>>(
        y3, neigh2, wp, ye, nullptr, nullptr,
        nullptr, nullptr, nullptr, nullptr, 0.f, nullptr);

    // 11: combine -> y4 raw + BN4
    combine_bn<96, 3, 64><<<N2_/64, 96>>>(
        ye, (long)N2_ * 96, y4, psum, psq,
        gp, bp, scl + 384, shf + 384, 1.f / N2_, ctrs + 5);

    // 12: final BN + ReLU -> d_out
    final_norm<<<(N2_ * 96 + 255) / 256, 256>>>(
        y4, scl + 384, shf + 384, (float*)d_out, N2_ * 96, 96);
}